// round 11
// baseline (speedup 1.0000x reference)
#include <cuda_runtime.h>
#include <cstdint>

// Lorenz RK4 over N=8M states — tuned smem-staged chassis (best harness
// performer). Block=256, 12KB tile, L2 policy hints. All global LDG/STG
// fully coalesced float4; the 12B-stride state access happens in smem.

#define DT     0.01f
#define SIGMA  10.0f
#define RHO    28.0f
#define BETA   (8.0f / 3.0f)

#define BLOCK_THREADS   256
#define STATES_PER_THR  4
#define STATES_PER_BLK  (BLOCK_THREADS * STATES_PER_THR)    // 1024
#define VEC4_PER_BLK    (STATES_PER_BLK * 3 / 4)            // 768 float4 = 12KB

__device__ __forceinline__ void lorenz_f(float x, float y, float z,
                                         float& dx, float& dy, float& dz) {
    dx = SIGMA * (y - x);
    dy = x * (RHO - z) - y;
    dz = x * y - BETA * z;
}

__device__ __forceinline__ void rk4_step(float& x, float& y, float& z) {
    const float h2 = 0.5f * DT;
    float k1x, k1y, k1z, k2x, k2y, k2z, k3x, k3y, k3z, k4x, k4y, k4z;

    lorenz_f(x, y, z, k1x, k1y, k1z);
    lorenz_f(x + h2 * k1x, y + h2 * k1y, z + h2 * k1z, k2x, k2y, k2z);
    lorenz_f(x + h2 * k2x, y + h2 * k2y, z + h2 * k2z, k3x, k3y, k3z);
    lorenz_f(x + DT * k3x, y + DT * k3y, z + DT * k3z, k4x, k4y, k4z);

    const float w = DT / 6.0f;
    x += w * (k1x + 2.0f * k2x + 2.0f * k3x + k4x);
    y += w * (k1y + 2.0f * k2y + 2.0f * k3y + k4y);
    z += w * (k1z + 2.0f * k2z + 2.0f * k3z + k4z);
}

__device__ __forceinline__ float4 ldg_pol(const float4* p, uint64_t pol) {
    float4 v;
    asm volatile("ld.global.nc.L2::cache_hint.v4.f32 {%0,%1,%2,%3}, [%4], %5;"
                 : "=f"(v.x), "=f"(v.y), "=f"(v.z), "=f"(v.w)
                 : "l"(p), "l"(pol));
    return v;
}

__device__ __forceinline__ void stg_pol(float4* p, float4 v, uint64_t pol) {
    asm volatile("st.global.L2::cache_hint.v4.f32 [%0], {%1,%2,%3,%4}, %5;"
                 :: "l"(p), "f"(v.x), "f"(v.y), "f"(v.z), "f"(v.w), "l"(pol)
                 : "memory");
}

__global__ void __launch_bounds__(BLOCK_THREADS)
lorenz_rk4_staged_kernel(const float4* __restrict__ in4,
                         float4* __restrict__ out4)
{
    __shared__ float4 tile[VEC4_PER_BLK];            // 12 KB

    const int tid  = threadIdx.x;
    const long long base = (long long)blockIdx.x * VEC4_PER_BLK;

    uint64_t pol_ld, pol_st;
    asm("createpolicy.fractional.L2::evict_last.b64  %0, 1.0;" : "=l"(pol_ld));
    asm("createpolicy.fractional.L2::evict_first.b64 %0, 1.0;" : "=l"(pol_st));

    // Phase 1: fully coalesced global -> smem (3x LDG.128 per thread).
    #pragma unroll
    for (int k = 0; k < 3; k++)
        tile[tid + k * BLOCK_THREADS] =
            ldg_pol(in4 + base + tid + k * BLOCK_THREADS, pol_ld);

    __syncthreads();

    // Phase 2: each thread owns 4 consecutive states = 12 contiguous floats
    // (3x LDS.128 at 48B stride: bank-conflict-free, period-8 in tid).
    float* my = (float*)tile + tid * 12;
    float s[12];
    #pragma unroll
    for (int k = 0; k < 3; k++) {
        float4 v = ((float4*)my)[k];
        s[4*k+0] = v.x; s[4*k+1] = v.y; s[4*k+2] = v.z; s[4*k+3] = v.w;
    }

    #pragma unroll
    for (int i = 0; i < STATES_PER_THR; i++)
        rk4_step(s[3*i + 0], s[3*i + 1], s[3*i + 2]);

    #pragma unroll
    for (int k = 0; k < 3; k++)
        ((float4*)my)[k] = make_float4(s[4*k+0], s[4*k+1], s[4*k+2], s[4*k+3]);

    __syncthreads();

    // Phase 3: fully coalesced smem -> global (3x STG.128 per thread).
    #pragma unroll
    for (int k = 0; k < 3; k++)
        stg_pol(out4 + base + tid + k * BLOCK_THREADS,
                tile[tid + k * BLOCK_THREADS], pol_st);
}

// Scalar tail: 8,000,000 = 7812 * 1024 + 512, so 512 states land here.
// Independent of the main grid; overlaps with it in the same stream order.
__global__ void
lorenz_rk4_tail_kernel(const float* __restrict__ in,
                       float* __restrict__ out,
                       int start, int n_states)
{
    int i = start + blockIdx.x * blockDim.x + threadIdx.x;
    if (i >= n_states) return;
    float x = in[3*i + 0];
    float y = in[3*i + 1];
    float z = in[3*i + 2];
    rk4_step(x, y, z);
    out[3*i + 0] = x;
    out[3*i + 1] = y;
    out[3*i + 2] = z;
}

extern "C" void kernel_launch(void* const* d_in, const int* in_sizes, int n_in,
                              void* d_out, int out_size)
{
    const float* in = (const float*)d_in[0];
    float* out = (float*)d_out;
    int n_states = in_sizes[0] / 3;                   // 8,000,000

    int n_full_blocks = n_states / STATES_PER_BLK;    // 7812
    if (n_full_blocks > 0)
        lorenz_rk4_staged_kernel<<<n_full_blocks, BLOCK_THREADS>>>(
            (const float4*)in, (float4*)out);

    int done = n_full_blocks * STATES_PER_BLK;
    int tail = n_states - done;                       // 512
    if (tail > 0) {
        int block = 256;
        int grid = (tail + block - 1) / block;
        lorenz_rk4_tail_kernel<<<grid, block>>>(in, out, done, n_states);
    }
}

// round 14
// speedup vs baseline: 1.1207x; 1.1207x over previous
#include <cuda_runtime.h>
#include <cstdint>

// Lorenz RK4 over N=8M states — champion kernel (R9 config).
// Block=128, 512 states/CTA (divides 8M exactly: 15625 blocks, NO tail
// launch). Smem-staged: all global LDG/STG fully coalesced float4; the
// 12B-stride per-state access happens in smem (bank-conflict-free).
// L2 policy hints: loads evict_last, stores evict_first.

#define DT     0.01f
#define SIGMA  10.0f
#define RHO    28.0f
#define BETA   (8.0f / 3.0f)

#define BLOCK_THREADS   128
#define STATES_PER_THR  4
#define STATES_PER_BLK  (BLOCK_THREADS * STATES_PER_THR)    // 512 = 2^9
#define VEC4_PER_BLK    (STATES_PER_BLK * 3 / 4)            // 384 float4 = 6KB

__device__ __forceinline__ void lorenz_f(float x, float y, float z,
                                         float& dx, float& dy, float& dz) {
    dx = SIGMA * (y - x);
    dy = x * (RHO - z) - y;
    dz = x * y - BETA * z;
}

__device__ __forceinline__ void rk4_step(float& x, float& y, float& z) {
    const float h2 = 0.5f * DT;
    float k1x, k1y, k1z, k2x, k2y, k2z, k3x, k3y, k3z, k4x, k4y, k4z;

    lorenz_f(x, y, z, k1x, k1y, k1z);
    lorenz_f(x + h2 * k1x, y + h2 * k1y, z + h2 * k1z, k2x, k2y, k2z);
    lorenz_f(x + h2 * k2x, y + h2 * k2y, z + h2 * k2z, k3x, k3y, k3z);
    lorenz_f(x + DT * k3x, y + DT * k3y, z + DT * k3z, k4x, k4y, k4z);

    const float w = DT / 6.0f;
    x += w * (k1x + 2.0f * k2x + 2.0f * k3x + k4x);
    y += w * (k1y + 2.0f * k2y + 2.0f * k3y + k4y);
    z += w * (k1z + 2.0f * k2z + 2.0f * k3z + k4z);
}

__device__ __forceinline__ float4 ldg_pol(const float4* p, uint64_t pol) {
    float4 v;
    asm volatile("ld.global.nc.L2::cache_hint.v4.f32 {%0,%1,%2,%3}, [%4], %5;"
                 : "=f"(v.x), "=f"(v.y), "=f"(v.z), "=f"(v.w)
                 : "l"(p), "l"(pol));
    return v;
}

__device__ __forceinline__ void stg_pol(float4* p, float4 v, uint64_t pol) {
    asm volatile("st.global.L2::cache_hint.v4.f32 [%0], {%1,%2,%3,%4}, %5;"
                 :: "l"(p), "f"(v.x), "f"(v.y), "f"(v.z), "f"(v.w), "l"(pol)
                 : "memory");
}

__global__ void __launch_bounds__(BLOCK_THREADS)
lorenz_rk4_staged_kernel(const float4* __restrict__ in4,
                         float4* __restrict__ out4)
{
    __shared__ float4 tile[VEC4_PER_BLK];            // 6 KB

    const int tid  = threadIdx.x;
    const long long base = (long long)blockIdx.x * VEC4_PER_BLK;

    uint64_t pol_ld, pol_st;
    asm("createpolicy.fractional.L2::evict_last.b64  %0, 1.0;" : "=l"(pol_ld));
    asm("createpolicy.fractional.L2::evict_first.b64 %0, 1.0;" : "=l"(pol_st));

    // Phase 1: fully coalesced global -> smem (3x LDG.128 per thread).
    #pragma unroll
    for (int k = 0; k < 3; k++)
        tile[tid + k * BLOCK_THREADS] =
            ldg_pol(in4 + base + tid + k * BLOCK_THREADS, pol_ld);

    __syncthreads();

    // Phase 2: each thread owns 4 consecutive states = 12 contiguous floats
    // in smem (3x LDS.128 at 48B stride: bank-conflict-free).
    float* my = (float*)tile + tid * 12;
    float s[12];
    #pragma unroll
    for (int k = 0; k < 3; k++) {
        float4 v = ((float4*)my)[k];
        s[4*k+0] = v.x; s[4*k+1] = v.y; s[4*k+2] = v.z; s[4*k+3] = v.w;
    }

    #pragma unroll
    for (int i = 0; i < STATES_PER_THR; i++)
        rk4_step(s[3*i + 0], s[3*i + 1], s[3*i + 2]);

    #pragma unroll
    for (int k = 0; k < 3; k++)
        ((float4*)my)[k] = make_float4(s[4*k+0], s[4*k+1], s[4*k+2], s[4*k+3]);

    __syncthreads();

    // Phase 3: fully coalesced smem -> global (3x STG.128 per thread).
    #pragma unroll
    for (int k = 0; k < 3; k++)
        stg_pol(out4 + base + tid + k * BLOCK_THREADS,
                tile[tid + k * BLOCK_THREADS], pol_st);
}

// Scalar tail for N not divisible by STATES_PER_BLK.
// UNUSED for N=8M (15625 * 512 == 8,000,000 exactly -> zero tail launches).
__global__ void
lorenz_rk4_tail_kernel(const float* __restrict__ in,
                       float* __restrict__ out,
                       int start, int n_states)
{
    int i = start + blockIdx.x * blockDim.x + threadIdx.x;
    if (i >= n_states) return;
    float x = in[3*i + 0];
    float y = in[3*i + 1];
    float z = in[3*i + 2];
    rk4_step(x, y, z);
    out[3*i + 0] = x;
    out[3*i + 1] = y;
    out[3*i + 2] = z;
}

extern "C" void kernel_launch(void* const* d_in, const int* in_sizes, int n_in,
                              void* d_out, int out_size)
{
    const float* in = (const float*)d_in[0];
    float* out = (float*)d_out;
    int n_states = in_sizes[0] / 3;                   // 8,000,000

    int n_full_blocks = n_states / STATES_PER_BLK;    // 15625 for 8M
    if (n_full_blocks > 0)
        lorenz_rk4_staged_kernel<<<n_full_blocks, BLOCK_THREADS>>>(
            (const float4*)in, (float4*)out);

    int done = n_full_blocks * STATES_PER_BLK;
    int tail = n_states - done;                       // 0 for 8M
    if (tail > 0) {
        int block = 256;
        int grid = (tail + block - 1) / block;
        lorenz_rk4_tail_kernel<<<grid, block>>>(in, out, done, n_states);
    }
}